// round 8
// baseline (speedup 1.0000x reference)
#include <cuda_runtime.h>
#include <cuda_fp16.h>
#include <cstdint>
#include <cstddef>

#define TPB 256
#define NEG_SLOPE 0.01f
#define XSTRB 528                     /* X row stride bytes (256 fp16 + pad) */

/* smem byte offsets (per CTA: 68864 B -> 3 CTAs/SM) */
#define XHI_OFF 0
#define WB_OFF  33792                 /* 2 bufs x 16384 */
#define WBUF    16384
#define WLOD    8192                  /* lo region inside buf */
#define B1_OFF  66560
#define W2_OFF  67584
#define GR_OFF  68608
#define SMEM_TOTAL 68864

__device__ float g_H[(size_t)131072 * 256];
__device__ __align__(16) uint8_t g_Wsp[3 * 16 * 16384];   /* [which][kc][1024 chunks x 16B] */

__device__ __forceinline__ uint32_t smem_u32(const void* p) {
    uint32_t a;
    asm("{ .reg .u64 t; cvta.to.shared.u64 t, %1; cvt.u32.u64 %0, t; }" : "=r"(a) : "l"(p));
    return a;
}
__device__ __forceinline__ float lrelu(float x) {
    return fmaxf(x, 0.f) + NEG_SLOPE * fminf(x, 0.f);
}
__device__ __forceinline__ uint32_t pack_h2(float v0, float v1) {
    __half2 h = __floats2half2_rn(v0, v1);
    return *(uint32_t*)&h;
}
__device__ __forceinline__ void mma16816(float* c, const uint32_t* a, uint32_t b0, uint32_t b1) {
    asm("mma.sync.aligned.m16n8k16.row.col.f32.f16.f16.f32 "
        "{%0,%1,%2,%3},{%4,%5,%6,%7},{%8,%9},{%0,%1,%2,%3};"
        : "+f"(c[0]), "+f"(c[1]), "+f"(c[2]), "+f"(c[3])
        : "r"(a[0]), "r"(a[1]), "r"(a[2]), "r"(a[3]), "r"(b0), "r"(b1));
}
#define LDM_X4(r, a) \
    asm volatile("ldmatrix.sync.aligned.m8n8.x4.shared.b16 {%0,%1,%2,%3}, [%4];" \
        : "=r"((r)[0]), "=r"((r)[1]), "=r"((r)[2]), "=r"((r)[3]) : "r"(a))
#define CP16(dst, src) asm volatile("cp.async.cg.shared.global [%0], [%1], 16;" :: "r"(dst), "l"(src))
#define CP_COMMIT()    asm volatile("cp.async.commit_group;" ::: "memory")
#define CP_WAIT1()     asm volatile("cp.async.wait_group 1;" ::: "memory")

/* ---- prep: W[rows<=256][256] fp32 -> fp16 hi/lo 16B chunks per k-chunk ---- */
__global__ void prep_split(const float* __restrict__ W, int which, int wrows) {
    int c = blockIdx.x * blockDim.x + threadIdx.x;   /* 0..16383 */
    int kc = c >> 10, j = c & 1023;
    int jj = j & 511, n = jj >> 1, kh = jj & 1;
    const float* src = W + (size_t)n * 256 + kc * 16 + kh * 8;
    float v[8];
#pragma unroll
    for (int q = 0; q < 8; q++) v[q] = (n < wrows) ? src[q] : 0.f;
    uint32_t h[4], l[4];
#pragma unroll
    for (int q = 0; q < 4; q++) {
        __half2 hh = __floats2half2_rn(v[2 * q], v[2 * q + 1]);
        float2 hf = __half22float2(hh);
        __half2 ll = __floats2half2_rn(v[2 * q] - hf.x, v[2 * q + 1] - hf.y);
        h[q] = *(uint32_t*)&hh;
        l[q] = *(uint32_t*)&ll;
    }
    uint4 out = (j < 512) ? make_uint4(h[0], h[1], h[2], h[3])
                          : make_uint4(l[0], l[1], l[2], l[3]);
    *(uint4*)(g_Wsp + ((size_t)which * 16 + kc) * 16384 + (size_t)j * 16) = out;
}

/* compact swizzled W store: row n at n*32 bytes, chunk-half h at (h*16)^((n&4)<<2) */
__device__ __forceinline__ void issue_w(uint32_t sb, const uint8_t* wsrc, int kc, int tid) {
    if (kc <= 15) {
        uint32_t buf = sb + WB_OFF + (kc & 1) * WBUF;
        const uint8_t* src = wsrc + (size_t)kc * 16384 + (size_t)tid * 16;
#pragma unroll
        for (int i = 0; i < 4; i++) {
            int j = tid + 256 * i;
            int jj = j & 511, n = jj >> 1, h = jj & 1;
            uint32_t dst = buf + ((j >> 9) ? WLOD : 0) + n * 32 + ((h << 4) ^ ((n & 4) << 2));
            CP16(dst, src + i * 4096);
        }
    }
    CP_COMMIT();
}

/* PASS 0: blocks [0,nbB) bond head, [nbB,..) stems L1 -> g_H | PASS 1: stems L2 */
template<int PASS>
__global__ void __launch_bounds__(TPB, 3)
mlp_kernel(const float* __restrict__ atom,
           const float* __restrict__ b_b1, const float* __restrict__ w_b2,
           const float* __restrict__ b_b2, const float* __restrict__ b_s1,
           const float* __restrict__ b_s2, const int* __restrict__ slices,
           const int* __restrict__ bd_b, const int* __restrict__ bonds,
           const int* __restrict__ st_b, const int* __restrict__ st_a,
           float* __restrict__ out_bond, float* __restrict__ out_stem, int nbB) {
    extern __shared__ char sm[];
    uint32_t sb = smem_u32(sm);
    int tid = threadIdx.x, lid = tid & 31, wn = tid >> 5;
    int mode = (PASS == 1) ? 2 : ((int)blockIdx.x < nbB ? 1 : 0);
    int row_base = (PASS == 1) ? blockIdx.x * 64
                 : (mode == 1 ? blockIdx.x * 64 : (blockIdx.x - nbB) * 64);
    int widx = (PASS == 1) ? 2 : (mode == 1 ? 0 : 1);
    const uint8_t* wsrc = g_Wsp + (size_t)widx * 262144;

    int*   grow = (int*)(sm + GR_OFF);
    float* b1s  = (float*)(sm + B1_OFF);
    float* w2s  = (float*)(sm + W2_OFF);

    if (tid < 64) {
        int r = row_base + tid, g;
        if (PASS == 1)       g = r;
        else if (mode == 1)  { int bd = r >> 1; g = slices[bd_b[bd]] + bonds[2 * bd + (r & 1)]; }
        else                 g = slices[st_b[r]] + st_a[r];
        grow[tid] = g;
    }
    if (PASS == 1) b1s[tid] = (tid < 105) ? b_s2[tid] : 0.f;
    else           b1s[tid] = (mode == 1) ? b_b1[tid] : b_s1[tid];
    if (PASS == 0 && mode == 1) w2s[tid] = w_b2[tid];
    __syncthreads();

    issue_w(sb, wsrc, 0, tid);
    issue_w(sb, wsrc, 1, tid);

    /* ---- X gather + fp16 hi store: thread = (row, quarter) ---- */
    {
        const float* Asrc = (PASS == 1) ? (const float*)g_H : atom;
        int row = tid >> 2, q4 = tid & 3;
        const float4* src = (const float4*)(Asrc + (size_t)grow[row] * 256 + q4 * 64);
        char* xh = sm + XHI_OFF + row * XSTRB + q4 * 128;
#pragma unroll
        for (int q = 0; q < 16; q++) {
            float4 v = src[q];
            *(uint2*)(xh + q * 8) = make_uint2(pack_h2(v.x, v.y), pack_h2(v.z, v.w));
        }
    }

    float acc[4][4][4];
#pragma unroll
    for (int mt = 0; mt < 4; mt++)
#pragma unroll
        for (int nt = 0; nt < 4; nt++)
#pragma unroll
            for (int j = 0; j < 4; j++) acc[mt][nt][j] = 0.f;

    int qr = lid >> 2, qc = lid & 3;

    uint32_t xab = sb + XHI_OFF + (uint32_t)(lid & 15) * XSTRB + ((lid >> 4) << 4);
    uint32_t wa0;
    {
        int n = wn * 32 + (lid & 7) + ((lid >> 4) << 3);
        int kh = (lid >> 3) & 1;
        wa0 = (uint32_t)(n * 32 + ((kh << 4) ^ ((n & 4) << 2)));
    }

    __syncthreads();     /* X visible */

#pragma unroll 1
    for (int kc = 0; kc < 16; kc++) {
        CP_WAIT1();
        __syncthreads();

        uint32_t bh[2][4], bl[2][4];
        uint32_t bb = sb + WB_OFF + (kc & 1) * WBUF;
#pragma unroll
        for (int np = 0; np < 2; np++) {
            LDM_X4(bh[np], bb + wa0 + np * 512);
            LDM_X4(bl[np], bb + wa0 + np * 512 + WLOD);
        }
#pragma unroll
        for (int mt = 0; mt < 4; mt++) {
            uint32_t ah[4];
            LDM_X4(ah, xab + mt * (16 * XSTRB) + kc * 32);
#pragma unroll
            for (int np = 0; np < 2; np++) {
                mma16816(acc[mt][2 * np],     ah, bh[np][0], bh[np][1]);
                mma16816(acc[mt][2 * np + 1], ah, bh[np][2], bh[np][3]);
                mma16816(acc[mt][2 * np],     ah, bl[np][0], bl[np][1]);
                mma16816(acc[mt][2 * np + 1], ah, bl[np][2], bl[np][3]);
            }
        }
        __syncthreads();               /* all reads of buf kc&1 done */
        issue_w(sb, wsrc, kc + 2, tid);
    }

    /* ================= epilogue ================= */
    if (PASS == 0 && mode == 1) {
        float* ysm = (float*)(sm + WB_OFF);   /* [8 wn][64 rows] */
#pragma unroll
        for (int mt = 0; mt < 4; mt++)
#pragma unroll
            for (int jr = 0; jr < 2; jr++) {
                float s = 0.f;
#pragma unroll
                for (int nt = 0; nt < 4; nt++) {
                    int c = wn * 32 + nt * 8 + 2 * qc;
                    s += lrelu(acc[mt][nt][2 * jr]     + b1s[c])     * w2s[c];
                    s += lrelu(acc[mt][nt][2 * jr + 1] + b1s[c + 1]) * w2s[c + 1];
                }
                s += __shfl_xor_sync(0xffffffffu, s, 1);
                s += __shfl_xor_sync(0xffffffffu, s, 2);
                if (qc == 0)
                    ysm[wn * 64 + mt * 16 + qr + 8 * jr] = s;
            }
        __syncthreads();
        if (tid < 64) {
            float y = 0.f;
#pragma unroll
            for (int w = 0; w < 8; w++) y += ysm[w * 64 + tid];
            float y2 = __shfl_down_sync(0xffffffffu, y, 1);
            if (!(tid & 1))
                out_bond[(row_base + tid) >> 1] = 0.5f * (y + y2) + b_b2[0];
        }
    } else if (PASS == 0) { /* stems L1 */
#pragma unroll
        for (int mt = 0; mt < 4; mt++)
#pragma unroll
            for (int jr = 0; jr < 2; jr++) {
                size_t row = (size_t)row_base + mt * 16 + qr + 8 * jr;
#pragma unroll
                for (int nt = 0; nt < 4; nt++) {
                    int c = wn * 32 + nt * 8 + 2 * qc;
                    float v0 = lrelu(acc[mt][nt][2 * jr]     + b1s[c]);
                    float v1 = lrelu(acc[mt][nt][2 * jr + 1] + b1s[c + 1]);
                    *(float2*)(g_H + row * 256 + c) = make_float2(v0, v1);
                }
            }
    } else { /* stems L2 */
#pragma unroll
        for (int mt = 0; mt < 4; mt++)
#pragma unroll
            for (int jr = 0; jr < 2; jr++) {
                size_t row = (size_t)row_base + mt * 16 + qr + 8 * jr;
#pragma unroll
                for (int nt = 0; nt < 4; nt++) {
                    int c = wn * 32 + nt * 8 + 2 * qc;
                    if (c < 105)
                        out_stem[row * 105 + c] = acc[mt][nt][2 * jr] + b1s[c];
                    if (c + 1 < 105)
                        out_stem[row * 105 + c + 1] = acc[mt][nt][2 * jr + 1] + b1s[c + 1];
                }
            }
    }
}

extern "C" void kernel_launch(void* const* d_in, const int* in_sizes, int n_in,
                              void* d_out, int out_size) {
    const float* atom = (const float*)d_in[0];
    const float* mol  = (const float*)d_in[1];
    const float* w_s1 = (const float*)d_in[2];
    const float* b_s1 = (const float*)d_in[3];
    const float* w_s2 = (const float*)d_in[4];
    const float* b_s2 = (const float*)d_in[5];
    const float* w_b1 = (const float*)d_in[6];
    const float* b_b1 = (const float*)d_in[7];
    const float* w_b2 = (const float*)d_in[8];
    const float* b_b2 = (const float*)d_in[9];
    const int* slices = (const int*)d_in[10];
    const int* st_b   = (const int*)d_in[11];
    const int* st_a   = (const int*)d_in[12];
    const int* bonds  = (const int*)d_in[13];
    const int* bd_b   = (const int*)d_in[14];

    int n_stems = in_sizes[11];
    int n_mol   = in_sizes[1];
    int n_bonds = in_sizes[14];

    float* out      = (float*)d_out;
    float* out_stem = out;
    float* out_mol  = out + (size_t)n_stems * 105;
    float* out_bond = out_mol + n_mol;

    cudaFuncSetAttribute(mlp_kernel<0>, cudaFuncAttributeMaxDynamicSharedMemorySize, SMEM_TOTAL);
    cudaFuncSetAttribute(mlp_kernel<1>, cudaFuncAttributeMaxDynamicSharedMemorySize, SMEM_TOTAL);

    cudaMemcpyAsync(out_mol, mol, (size_t)n_mol * sizeof(float), cudaMemcpyDeviceToDevice);

    prep_split<<<64, 256>>>(w_b1, 0, 256);
    prep_split<<<64, 256>>>(w_s1, 1, 256);
    prep_split<<<64, 256>>>(w_s2, 2, 105);

    int nbB = (2 * n_bonds) / 64;
    int nsB = n_stems / 64;
    mlp_kernel<0><<<nbB + nsB, TPB, SMEM_TOTAL>>>(
        atom, b_b1, w_b2, b_b2, b_s1, b_s2, slices, bd_b, bonds, st_b, st_a,
        out_bond, out_stem, nbB);
    mlp_kernel<1><<<nsB, TPB, SMEM_TOTAL>>>(
        atom, b_b1, w_b2, b_b2, b_s1, b_s2, slices, bd_b, bonds, st_b, st_a,
        out_bond, out_stem, 0);
}

// round 10
// speedup vs baseline: 1.6713x; 1.6713x over previous
#include <cuda_runtime.h>
#include <cuda_fp16.h>
#include <cstdint>
#include <cstddef>

#define TPB 256
#define NEG_SLOPE 0.01f
#define XSTRB 528                     /* X row stride bytes (256 fp16 + pad) */

/* smem byte offsets (per CTA: 102912 B -> 2 CTAs/SM) */
#define XHI_OFF 0
#define WB_OFF  67584                 /* 4 bufs x 8192 */
#define WBUF    8192
#define WLOD    4096                  /* lo region inside buf */
#define B1_OFF  100352
#define W2_OFF  101376
#define GR_OFF  102400
#define SMEM_TOTAL 102912

__device__ float g_H[(size_t)131072 * 256];
__device__ __align__(16) uint8_t g_Wsp[3 * 16 * 16384];   /* [which][kc][hi 512|lo 512 chunks x 16B] */

__device__ __forceinline__ uint32_t smem_u32(const void* p) {
    uint32_t a;
    asm("{ .reg .u64 t; cvta.to.shared.u64 t, %1; cvt.u32.u64 %0, t; }" : "=r"(a) : "l"(p));
    return a;
}
__device__ __forceinline__ float lrelu(float x) {
    return fmaxf(x, 0.f) + NEG_SLOPE * fminf(x, 0.f);
}
__device__ __forceinline__ uint32_t pack_h2(float v0, float v1) {
    __half2 h = __floats2half2_rn(v0, v1);
    return *(uint32_t*)&h;
}
__device__ __forceinline__ void mma16816(float* c, const uint32_t* a, uint32_t b0, uint32_t b1) {
    asm("mma.sync.aligned.m16n8k16.row.col.f32.f16.f16.f32 "
        "{%0,%1,%2,%3},{%4,%5,%6,%7},{%8,%9},{%0,%1,%2,%3};"
        : "+f"(c[0]), "+f"(c[1]), "+f"(c[2]), "+f"(c[3])
        : "r"(a[0]), "r"(a[1]), "r"(a[2]), "r"(a[3]), "r"(b0), "r"(b1));
}
#define LDM_X4(r, a) \
    asm volatile("ldmatrix.sync.aligned.m8n8.x4.shared.b16 {%0,%1,%2,%3}, [%4];" \
        : "=r"((r)[0]), "=r"((r)[1]), "=r"((r)[2]), "=r"((r)[3]) : "r"(a))
#define CP16(dst, src) asm volatile("cp.async.cg.shared.global [%0], [%1], 16;" :: "r"(dst), "l"(src))
#define CP_COMMIT()    asm volatile("cp.async.commit_group;" ::: "memory")
#define CP_WAIT2()     asm volatile("cp.async.wait_group 2;" ::: "memory")

/* ---- prep: W[rows<=256][256] fp32 -> fp16 hi/lo 16B chunks per k-chunk ---- */
__global__ void prep_split(const float* __restrict__ W, int which, int wrows) {
    int c = blockIdx.x * blockDim.x + threadIdx.x;   /* 0..16383 */
    int kc = c >> 10, j = c & 1023;
    int jj = j & 511, n = jj >> 1, kh = jj & 1;
    const float* src = W + (size_t)n * 256 + kc * 16 + kh * 8;
    float v[8];
#pragma unroll
    for (int q = 0; q < 8; q++) v[q] = (n < wrows) ? src[q] : 0.f;
    uint32_t h[4], l[4];
#pragma unroll
    for (int q = 0; q < 4; q++) {
        __half2 hh = __floats2half2_rn(v[2 * q], v[2 * q + 1]);
        float2 hf = __half22float2(hh);
        __half2 ll = __floats2half2_rn(v[2 * q] - hf.x, v[2 * q + 1] - hf.y);
        h[q] = *(uint32_t*)&hh;
        l[q] = *(uint32_t*)&ll;
    }
    uint4 out = (j < 512) ? make_uint4(h[0], h[1], h[2], h[3])
                          : make_uint4(l[0], l[1], l[2], l[3]);
    *(uint4*)(g_Wsp + ((size_t)which * 16 + kc) * 16384 + (size_t)j * 16) = out;
}

/* W stage for iteration it (nh = it>>4, kc = it&15): 8KB = 128 n-rows hi+lo */
__device__ __forceinline__ void issue_w(uint32_t sb, const uint8_t* wsrc, int it,
                                        int tid, int niter) {
    if (it < niter) {
        int nh = it >> 4, kc = it & 15;
        uint32_t buf = sb + WB_OFF + (it & 3) * WBUF;
        const uint8_t* srcb = wsrc + (size_t)kc * 16384 + (size_t)(nh * 256 + tid) * 16;
        int n = tid >> 1, kh = tid & 1;
        uint32_t dst = buf + n * 32 + ((kh << 4) ^ ((n & 4) << 2));
        CP16(dst, srcb);                    /* hi */
        CP16(dst + WLOD, srcb + 8192);      /* lo */
    }
    CP_COMMIT();
}

/* PASS 0: blocks [0,nbB) bond head, [nbB,..) stems L1 -> g_H | PASS 1: stems L2 */
template<int PASS>
__global__ void __launch_bounds__(TPB, 2)
mlp_kernel(const float* __restrict__ atom,
           const float* __restrict__ b_b1, const float* __restrict__ w_b2,
           const float* __restrict__ b_b2, const float* __restrict__ b_s1,
           const float* __restrict__ b_s2, const int* __restrict__ slices,
           const int* __restrict__ bd_b, const int* __restrict__ bonds,
           const int* __restrict__ st_b, const int* __restrict__ st_a,
           float* __restrict__ out_bond, float* __restrict__ out_stem, int nbB) {
    constexpr int NH = (PASS == 1) ? 1 : 2;
    constexpr int NITER = NH * 16;
    extern __shared__ char sm[];
    uint32_t sb = smem_u32(sm);
    int tid = threadIdx.x, lid = tid & 31, wid = tid >> 5;
    int wm = wid & 1, wn = wid >> 1;
    int mode = (PASS == 1) ? 2 : ((int)blockIdx.x < nbB ? 1 : 0);
    int row_base = (PASS == 1) ? blockIdx.x * 128
                 : (mode == 1 ? blockIdx.x * 128 : (blockIdx.x - nbB) * 128);
    int widx = (PASS == 1) ? 2 : (mode == 1 ? 0 : 1);
    const uint8_t* wsrc = g_Wsp + (size_t)widx * 262144;

    int*   grow = (int*)(sm + GR_OFF);
    float* b1s  = (float*)(sm + B1_OFF);
    float* w2s  = (float*)(sm + W2_OFF);

    if (tid < 128) {
        int r = row_base + tid, g;
        if (PASS == 1)       g = r;
        else if (mode == 1)  { int bd = r >> 1; g = slices[bd_b[bd]] + bonds[2 * bd + (r & 1)]; }
        else                 g = slices[st_b[r]] + st_a[r];
        grow[tid] = g;
    }
    if (PASS == 1) b1s[tid] = (tid < 105) ? b_s2[tid] : 0.f;
    else           b1s[tid] = (mode == 1) ? b_b1[tid] : b_s1[tid];
    if (PASS == 0 && mode == 1) w2s[tid] = w_b2[tid];
    __syncthreads();

    issue_w(sb, wsrc, 0, tid, NITER);
    issue_w(sb, wsrc, 1, tid, NITER);
    issue_w(sb, wsrc, 2, tid, NITER);

    /* ---- X gather + fp16-hi store: thread = (row, half = 128 floats = 32 float4) ---- */
    {
        const float* Asrc = (PASS == 1) ? (const float*)g_H : atom;
        int row = tid >> 1, h = tid & 1;
        const float4* src = (const float4*)(Asrc + (size_t)grow[row] * 256 + h * 128);
        char* xh = sm + XHI_OFF + row * XSTRB + h * 256;
#pragma unroll
        for (int q = 0; q < 32; q++) {
            float4 v = src[q];
            *(uint2*)(xh + q * 8) = make_uint2(pack_h2(v.x, v.y), pack_h2(v.z, v.w));
        }
    }
    __syncthreads();

    float acc[4][4][4];
#pragma unroll
    for (int mt = 0; mt < 4; mt++)
#pragma unroll
        for (int nt = 0; nt < 4; nt++)
#pragma unroll
            for (int j = 0; j < 4; j++) acc[mt][nt][j] = 0.f;
    float ybond[8];
#pragma unroll
    for (int i = 0; i < 8; i++) ybond[i] = 0.f;

    int qr = lid >> 2, qc = lid & 3;
    uint32_t xab = sb + XHI_OFF + (uint32_t)(wm * 64 + (lid & 15)) * XSTRB + ((lid >> 4) << 4);
    uint32_t wa[2];
#pragma unroll
    for (int np = 0; np < 2; np++) {
        int n = wn * 32 + np * 16 + (lid & 7) + ((lid >> 4) << 3);
        int kh = (lid >> 3) & 1;
        wa[np] = (uint32_t)(n * 32 + ((kh << 4) ^ ((n & 4) << 2)));
    }

#pragma unroll 1
    for (int nh = 0; nh < NH; nh++) {
#pragma unroll 1
        for (int kc = 0; kc < 16; kc++) {
            int it = nh * 16 + kc;
            CP_WAIT2();
            __syncthreads();
            issue_w(sb, wsrc, it + 3, tid, NITER);

            uint32_t bb = sb + WB_OFF + (it & 3) * WBUF;
            uint32_t bh[2][4], bl[2][4];
#pragma unroll
            for (int np = 0; np < 2; np++) {
                LDM_X4(bh[np], bb + wa[np]);
                LDM_X4(bl[np], bb + wa[np] + WLOD);
            }
#pragma unroll
            for (int mt = 0; mt < 4; mt++) {
                uint32_t ah[4];
                LDM_X4(ah, xab + mt * (16 * XSTRB) + kc * 32);
#pragma unroll
                for (int np = 0; np < 2; np++) {
                    mma16816(acc[mt][2 * np],     ah, bh[np][0], bh[np][1]);
                    mma16816(acc[mt][2 * np + 1], ah, bh[np][2], bh[np][3]);
                    mma16816(acc[mt][2 * np],     ah, bl[np][0], bl[np][1]);
                    mma16816(acc[mt][2 * np + 1], ah, bl[np][2], bl[np][3]);
                }
            }
        }
        /* ---- half-epilogue on N-half nh ---- */
        if (PASS == 0 && mode == 1) {
#pragma unroll
            for (int mt = 0; mt < 4; mt++)
#pragma unroll
                for (int jr = 0; jr < 2; jr++) {
                    float s = 0.f;
#pragma unroll
                    for (int nt = 0; nt < 4; nt++) {
                        int c = nh * 128 + wn * 32 + nt * 8 + 2 * qc;
                        s += lrelu(acc[mt][nt][2 * jr]     + b1s[c])     * w2s[c];
                        s += lrelu(acc[mt][nt][2 * jr + 1] + b1s[c + 1]) * w2s[c + 1];
                    }
                    ybond[mt * 2 + jr] += s;
                }
        } else if (PASS == 0) { /* stems L1: write this half's cols */
#pragma unroll
            for (int mt = 0; mt < 4; mt++)
#pragma unroll
                for (int jr = 0; jr < 2; jr++) {
                    size_t row = (size_t)row_base + wm * 64 + mt * 16 + qr + 8 * jr;
#pragma unroll
                    for (int nt = 0; nt < 4; nt++) {
                        int c = nh * 128 + wn * 32 + nt * 8 + 2 * qc;
                        float v0 = lrelu(acc[mt][nt][2 * jr]     + b1s[c]);
                        float v1 = lrelu(acc[mt][nt][2 * jr + 1] + b1s[c + 1]);
                        *(float2*)(g_H + row * 256 + c) = make_float2(v0, v1);
                    }
                }
        } else { /* PASS 1 (single half) */
#pragma unroll
            for (int mt = 0; mt < 4; mt++)
#pragma unroll
                for (int jr = 0; jr < 2; jr++) {
                    size_t row = (size_t)row_base + wm * 64 + mt * 16 + qr + 8 * jr;
#pragma unroll
                    for (int nt = 0; nt < 4; nt++) {
                        int c = wn * 32 + nt * 8 + 2 * qc;
                        if (c < 105)
                            out_stem[row * 105 + c] = acc[mt][nt][2 * jr] + b1s[c];
                        if (c + 1 < 105)
                            out_stem[row * 105 + c + 1] = acc[mt][nt][2 * jr + 1] + b1s[c + 1];
                    }
                }
        }
        if (nh == 0 && NH == 2) {  /* clear accumulators for second half */
#pragma unroll
            for (int mt = 0; mt < 4; mt++)
#pragma unroll
                for (int nt = 0; nt < 4; nt++)
#pragma unroll
                    for (int j = 0; j < 4; j++) acc[mt][nt][j] = 0.f;
        }
    }

    /* ---- bond final reduce across warps ---- */
    if (PASS == 0 && mode == 1) {
        __syncthreads();                       /* safe to reuse W buffers */
        float* ysm = (float*)(sm + WB_OFF);    /* [4 wn][128 rows] */
#pragma unroll
        for (int mt = 0; mt < 4; mt++)
#pragma unroll
            for (int jr = 0; jr < 2; jr++) {
                float s = ybond[mt * 2 + jr];
                s += __shfl_xor_sync(0xffffffffu, s, 1);
                s += __shfl_xor_sync(0xffffffffu, s, 2);
                if (qc == 0)
                    ysm[wn * 128 + wm * 64 + mt * 16 + qr + 8 * jr] = s;
            }
        __syncthreads();
        if (tid < 128) {
            float y = ysm[tid] + ysm[128 + tid] + ysm[256 + tid] + ysm[384 + tid];
            float y2 = __shfl_down_sync(0xffffffffu, y, 1);
            if (!(tid & 1))
                out_bond[(row_base + tid) >> 1] = 0.5f * (y + y2) + b_b2[0];
        }
    }
}

extern "C" void kernel_launch(void* const* d_in, const int* in_sizes, int n_in,
                              void* d_out, int out_size) {
    const float* atom = (const float*)d_in[0];
    const float* mol  = (const float*)d_in[1];
    const float* w_s1 = (const float*)d_in[2];
    const float* b_s1 = (const float*)d_in[3];
    const float* w_s2 = (const float*)d_in[4];
    const float* b_s2 = (const float*)d_in[5];
    const float* w_b1 = (const float*)d_in[6];
    const float* b_b1 = (const float*)d_in[7];
    const float* w_b2 = (const float*)d_in[8];
    const float* b_b2 = (const float*)d_in[9];
    const int* slices = (const int*)d_in[10];
    const int* st_b   = (const int*)d_in[11];
    const int* st_a   = (const int*)d_in[12];
    const int* bonds  = (const int*)d_in[13];
    const int* bd_b   = (const int*)d_in[14];

    int n_stems = in_sizes[11];
    int n_mol   = in_sizes[1];
    int n_bonds = in_sizes[14];

    float* out      = (float*)d_out;
    float* out_stem = out;
    float* out_mol  = out + (size_t)n_stems * 105;
    float* out_bond = out_mol + n_mol;

    cudaFuncSetAttribute(mlp_kernel<0>, cudaFuncAttributeMaxDynamicSharedMemorySize, SMEM_TOTAL);
    cudaFuncSetAttribute(mlp_kernel<1>, cudaFuncAttributeMaxDynamicSharedMemorySize, SMEM_TOTAL);

    cudaMemcpyAsync(out_mol, mol, (size_t)n_mol * sizeof(float), cudaMemcpyDeviceToDevice);

    prep_split<<<64, 256>>>(w_b1, 0, 256);
    prep_split<<<64, 256>>>(w_s1, 1, 256);
    prep_split<<<64, 256>>>(w_s2, 2, 105);

    int nbB = (2 * n_bonds) / 128;
    int nsB = n_stems / 128;
    mlp_kernel<0><<<nbB + nsB, TPB, SMEM_TOTAL>>>(
        atom, b_b1, w_b2, b_b2, b_s1, b_s2, slices, bd_b, bonds, st_b, st_a,
        out_bond, out_stem, nbB);
    mlp_kernel<1><<<nsB, TPB, SMEM_TOTAL>>>(
        atom, b_b1, w_b2, b_b2, b_s1, b_s2, slices, bd_b, bonds, st_b, st_a,
        out_bond, out_stem, 0);
}

// round 11
// speedup vs baseline: 1.7357x; 1.0385x over previous
#include <cuda_runtime.h>
#include <cuda_fp16.h>
#include <cstdint>
#include <cstddef>

#define TPB 256
#define NEG_SLOPE 0.01f
#define XSTRB 528                     /* X row stride bytes (256 fp16 + pad) */

/* smem byte offsets (per CTA: 102912 B -> 2 CTAs/SM) */
#define XHI_OFF 0
#define WB_OFF  67584                 /* 4 bufs x 8192 */
#define WBUF    8192
#define WLOD    4096                  /* lo region inside buf */
#define B1_OFF  100352
#define W2_OFF  101376
#define GR_OFF  102400
#define SMEM_TOTAL 102912

__device__ float g_H[(size_t)131072 * 256];
__device__ __align__(16) uint8_t g_Wsp[3 * 16 * 16384];   /* [which][kc][hi 512|lo 512 chunks x 16B] */

__device__ __forceinline__ uint32_t smem_u32(const void* p) {
    uint32_t a;
    asm("{ .reg .u64 t; cvta.to.shared.u64 t, %1; cvt.u32.u64 %0, t; }" : "=r"(a) : "l"(p));
    return a;
}
__device__ __forceinline__ float lrelu(float x) {
    return fmaxf(x, 0.f) + NEG_SLOPE * fminf(x, 0.f);
}
__device__ __forceinline__ uint32_t pack_h2(float v0, float v1) {
    __half2 h = __floats2half2_rn(v0, v1);
    return *(uint32_t*)&h;
}
__device__ __forceinline__ void mma16816(float* c, const uint32_t* a, uint32_t b0, uint32_t b1) {
    asm("mma.sync.aligned.m16n8k16.row.col.f32.f16.f16.f32 "
        "{%0,%1,%2,%3},{%4,%5,%6,%7},{%8,%9},{%0,%1,%2,%3};"
        : "+f"(c[0]), "+f"(c[1]), "+f"(c[2]), "+f"(c[3])
        : "r"(a[0]), "r"(a[1]), "r"(a[2]), "r"(a[3]), "r"(b0), "r"(b1));
}
#define LDM_X4(r, a) \
    asm volatile("ldmatrix.sync.aligned.m8n8.x4.shared.b16 {%0,%1,%2,%3}, [%4];" \
        : "=r"((r)[0]), "=r"((r)[1]), "=r"((r)[2]), "=r"((r)[3]) : "r"(a))
#define CP16(dst, src) asm volatile("cp.async.cg.shared.global [%0], [%1], 16;" :: "r"(dst), "l"(src))
#define CP_COMMIT()    asm volatile("cp.async.commit_group;" ::: "memory")
#define CP_WAIT2()     asm volatile("cp.async.wait_group 2;" ::: "memory")
#define PAIR_BAR(id)   asm volatile("bar.sync %0, 64;" :: "r"(id) : "memory")

/* ---- prep: W[rows<=256][256] fp32 -> fp16 hi/lo 16B chunks per k-chunk ---- */
__global__ void prep_split(const float* __restrict__ W, int which, int wrows) {
    int c = blockIdx.x * blockDim.x + threadIdx.x;   /* 0..16383 */
    int kc = c >> 10, j = c & 1023;
    int jj = j & 511, n = jj >> 1, kh = jj & 1;
    const float* src = W + (size_t)n * 256 + kc * 16 + kh * 8;
    float v[8];
#pragma unroll
    for (int q = 0; q < 8; q++) v[q] = (n < wrows) ? src[q] : 0.f;
    uint32_t h[4], l[4];
#pragma unroll
    for (int q = 0; q < 4; q++) {
        __half2 hh = __floats2half2_rn(v[2 * q], v[2 * q + 1]);
        float2 hf = __half22float2(hh);
        __half2 ll = __floats2half2_rn(v[2 * q] - hf.x, v[2 * q + 1] - hf.y);
        h[q] = *(uint32_t*)&hh;
        l[q] = *(uint32_t*)&ll;
    }
    uint4 out = (j < 512) ? make_uint4(h[0], h[1], h[2], h[3])
                          : make_uint4(l[0], l[1], l[2], l[3]);
    *(uint4*)(g_Wsp + ((size_t)which * 16 + kc) * 16384 + (size_t)j * 16) = out;
}

/* per-pair W slice stage: warp-pair wn stages its 32 n-rows (hi+lo) for iter it.
   ptid = wm*32+lid (0..63); 2 x CP16 per thread = 128 per pair = 2KB slice. */
__device__ __forceinline__ void issue_w_pair(uint32_t sb, const uint8_t* wsrc, int it,
                                             int wn, int ptid, int niter) {
    if (it < niter) {
        int nh = it >> 4, kc = it & 15;
        uint32_t buf = sb + WB_OFF + (it & 3) * WBUF;
#pragma unroll
        for (int e2 = 0; e2 < 2; e2++) {
            int e = ptid * 2 + e2;
            int np = e >> 2, rest = e & 3;
            int hl = rest >> 1, kh = rest & 1;
            int n = wn * 32 + np;
            int ng = nh * 128 + n;
            uint32_t dst = buf + n * 32 + ((kh << 4) ^ ((n & 4) << 2)) + hl * WLOD;
            const uint8_t* src = wsrc + (size_t)kc * 16384
                               + (size_t)(ng * 2 + kh) * 16 + (size_t)hl * 8192;
            CP16(dst, src);
        }
    }
    CP_COMMIT();
}

/* PASS 0: blocks [0,nbB) bond head, [nbB,..) stems L1 -> g_H | PASS 1: stems L2 */
template<int PASS>
__global__ void __launch_bounds__(TPB, 2)
mlp_kernel(const float* __restrict__ atom,
           const float* __restrict__ b_b1, const float* __restrict__ w_b2,
           const float* __restrict__ b_b2, const float* __restrict__ b_s1,
           const float* __restrict__ b_s2, const int* __restrict__ slices,
           const int* __restrict__ bd_b, const int* __restrict__ bonds,
           const int* __restrict__ st_b, const int* __restrict__ st_a,
           float* __restrict__ out_bond, float* __restrict__ out_stem, int nbB) {
    constexpr int NH = (PASS == 1) ? 1 : 2;
    constexpr int NITER = NH * 16;
    extern __shared__ char sm[];
    uint32_t sb = smem_u32(sm);
    int tid = threadIdx.x, lid = tid & 31, wid = tid >> 5;
    int wm = wid & 1, wn = wid >> 1;
    int ptid = wm * 32 + lid;
    int mode = (PASS == 1) ? 2 : ((int)blockIdx.x < nbB ? 1 : 0);
    int row_base = (PASS == 1) ? blockIdx.x * 128
                 : (mode == 1 ? blockIdx.x * 128 : (blockIdx.x - nbB) * 128);
    int widx = (PASS == 1) ? 2 : (mode == 1 ? 0 : 1);
    const uint8_t* wsrc = g_Wsp + (size_t)widx * 262144;

    int*   grow = (int*)(sm + GR_OFF);
    float* b1s  = (float*)(sm + B1_OFF);
    float* w2s  = (float*)(sm + W2_OFF);

    if (tid < 128) {
        int r = row_base + tid, g;
        if (PASS == 1)       g = r;
        else if (mode == 1)  { int bd = r >> 1; g = slices[bd_b[bd]] + bonds[2 * bd + (r & 1)]; }
        else                 g = slices[st_b[r]] + st_a[r];
        grow[tid] = g;
    }
    if (PASS == 1) b1s[tid] = (tid < 105) ? b_s2[tid] : 0.f;
    else           b1s[tid] = (mode == 1) ? b_b1[tid] : b_s1[tid];
    if (PASS == 0 && mode == 1) w2s[tid] = w_b2[tid];
    __syncthreads();

    issue_w_pair(sb, wsrc, 0, wn, ptid, NITER);
    issue_w_pair(sb, wsrc, 1, wn, ptid, NITER);
    issue_w_pair(sb, wsrc, 2, wn, ptid, NITER);

    /* ---- X gather + fp16-hi store: thread = (row, half = 128 floats) ---- */
    {
        const float* Asrc = (PASS == 1) ? (const float*)g_H : atom;
        int row = tid >> 1, h = tid & 1;
        const float4* src = (const float4*)(Asrc + (size_t)grow[row] * 256 + h * 128);
        char* xh = sm + XHI_OFF + row * XSTRB + h * 256;
#pragma unroll
        for (int q = 0; q < 32; q++) {
            float4 v = src[q];
            *(uint2*)(xh + q * 8) = make_uint2(pack_h2(v.x, v.y), pack_h2(v.z, v.w));
        }
    }
    __syncthreads();    /* X visible; only block-wide barrier before epilogue */

    float acc[4][4][4];
#pragma unroll
    for (int mt = 0; mt < 4; mt++)
#pragma unroll
        for (int nt = 0; nt < 4; nt++)
#pragma unroll
            for (int j = 0; j < 4; j++) acc[mt][nt][j] = 0.f;
    float ybond[8];
#pragma unroll
    for (int i = 0; i < 8; i++) ybond[i] = 0.f;

    int qr = lid >> 2, qc = lid & 3;
    uint32_t xab = sb + XHI_OFF + (uint32_t)(wm * 64 + (lid & 15)) * XSTRB + ((lid >> 4) << 4);
    uint32_t wa[2];
#pragma unroll
    for (int np = 0; np < 2; np++) {
        int n = wn * 32 + np * 16 + (lid & 7) + ((lid >> 4) << 3);
        int kh = (lid >> 3) & 1;
        wa[np] = (uint32_t)(n * 32 + ((kh << 4) ^ ((n & 4) << 2)));
    }

#pragma unroll 1
    for (int nh = 0; nh < NH; nh++) {
#pragma unroll 1
        for (int kc = 0; kc < 16; kc++) {
            int it = nh * 16 + kc;
            CP_WAIT2();                 /* own groups: stage 'it' data landed */
            PAIR_BAR(wn + 1);           /* pair visibility + ring-reuse safety */
            issue_w_pair(sb, wsrc, it + 3, wn, ptid, NITER);

            uint32_t bb = sb + WB_OFF + (it & 3) * WBUF;
            uint32_t bh[2][4], bl[2][4];
#pragma unroll
            for (int np = 0; np < 2; np++) {
                LDM_X4(bh[np], bb + wa[np]);
                LDM_X4(bl[np], bb + wa[np] + WLOD);
            }
#pragma unroll
            for (int mt = 0; mt < 4; mt++) {
                uint32_t ah[4];
                LDM_X4(ah, xab + mt * (16 * XSTRB) + kc * 32);
#pragma unroll
                for (int np = 0; np < 2; np++) {
                    mma16816(acc[mt][2 * np],     ah, bh[np][0], bh[np][1]);
                    mma16816(acc[mt][2 * np + 1], ah, bh[np][2], bh[np][3]);
                    mma16816(acc[mt][2 * np],     ah, bl[np][0], bl[np][1]);
                    mma16816(acc[mt][2 * np + 1], ah, bl[np][2], bl[np][3]);
                }
            }
        }
        /* ---- half-epilogue on N-half nh ---- */
        if (PASS == 0 && mode == 1) {
#pragma unroll
            for (int mt = 0; mt < 4; mt++)
#pragma unroll
                for (int jr = 0; jr < 2; jr++) {
                    float s = 0.f;
#pragma unroll
                    for (int nt = 0; nt < 4; nt++) {
                        int c = nh * 128 + wn * 32 + nt * 8 + 2 * qc;
                        s += lrelu(acc[mt][nt][2 * jr]     + b1s[c])     * w2s[c];
                        s += lrelu(acc[mt][nt][2 * jr + 1] + b1s[c + 1]) * w2s[c + 1];
                    }
                    ybond[mt * 2 + jr] += s;
                }
        } else if (PASS == 0) { /* stems L1 */
#pragma unroll
            for (int mt = 0; mt < 4; mt++)
#pragma unroll
                for (int jr = 0; jr < 2; jr++) {
                    size_t row = (size_t)row_base + wm * 64 + mt * 16 + qr + 8 * jr;
#pragma unroll
                    for (int nt = 0; nt < 4; nt++) {
                        int c = nh * 128 + wn * 32 + nt * 8 + 2 * qc;
                        float v0 = lrelu(acc[mt][nt][2 * jr]     + b1s[c]);
                        float v1 = lrelu(acc[mt][nt][2 * jr + 1] + b1s[c + 1]);
                        *(float2*)(g_H + row * 256 + c) = make_float2(v0, v1);
                    }
                }
        } else { /* PASS 1 */
#pragma unroll
            for (int mt = 0; mt < 4; mt++)
#pragma unroll
                for (int jr = 0; jr < 2; jr++) {
                    size_t row = (size_t)row_base + wm * 64 + mt * 16 + qr + 8 * jr;
#pragma unroll
                    for (int nt = 0; nt < 4; nt++) {
                        int c = wn * 32 + nt * 8 + 2 * qc;
                        if (c < 105)
                            out_stem[row * 105 + c] = acc[mt][nt][2 * jr] + b1s[c];
                        if (c + 1 < 105)
                            out_stem[row * 105 + c + 1] = acc[mt][nt][2 * jr + 1] + b1s[c + 1];
                    }
                }
        }
        if (nh == 0 && NH == 2) {
#pragma unroll
            for (int mt = 0; mt < 4; mt++)
#pragma unroll
                for (int nt = 0; nt < 4; nt++)
#pragma unroll
                    for (int j = 0; j < 4; j++) acc[mt][nt][j] = 0.f;
        }
    }

    /* ---- bond final reduce across warps ---- */
    if (PASS == 0 && mode == 1) {
        __syncthreads();                       /* all warps done with W buffers */
        float* ysm = (float*)(sm + WB_OFF);    /* [4 wn][128 rows] */
#pragma unroll
        for (int mt = 0; mt < 4; mt++)
#pragma unroll
            for (int jr = 0; jr < 2; jr++) {
                float s = ybond[mt * 2 + jr];
                s += __shfl_xor_sync(0xffffffffu, s, 1);
                s += __shfl_xor_sync(0xffffffffu, s, 2);
                if (qc == 0)
                    ysm[wn * 128 + wm * 64 + mt * 16 + qr + 8 * jr] = s;
            }
        __syncthreads();
        if (tid < 128) {
            float y = ysm[tid] + ysm[128 + tid] + ysm[256 + tid] + ysm[384 + tid];
            float y2 = __shfl_down_sync(0xffffffffu, y, 1);
            if (!(tid & 1))
                out_bond[(row_base + tid) >> 1] = 0.5f * (y + y2) + b_b2[0];
        }
    }
}

extern "C" void kernel_launch(void* const* d_in, const int* in_sizes, int n_in,
                              void* d_out, int out_size) {
    const float* atom = (const float*)d_in[0];
    const float* mol  = (const float*)d_in[1];
    const float* w_s1 = (const float*)d_in[2];
    const float* b_s1 = (const float*)d_in[3];
    const float* w_s2 = (const float*)d_in[4];
    const float* b_s2 = (const float*)d_in[5];
    const float* w_b1 = (const float*)d_in[6];
    const float* b_b1 = (const float*)d_in[7];
    const float* w_b2 = (const float*)d_in[8];
    const float* b_b2 = (const float*)d_in[9];
    const int* slices = (const int*)d_in[10];
    const int* st_b   = (const int*)d_in[11];
    const int* st_a   = (const int*)d_in[12];
    const int* bonds  = (const int*)d_in[13];
    const int* bd_b   = (const int*)d_in[14];

    int n_stems = in_sizes[11];
    int n_mol   = in_sizes[1];
    int n_bonds = in_sizes[14];

    float* out      = (float*)d_out;
    float* out_stem = out;
    float* out_mol  = out + (size_t)n_stems * 105;
    float* out_bond = out_mol + n_mol;

    cudaFuncSetAttribute(mlp_kernel<0>, cudaFuncAttributeMaxDynamicSharedMemorySize, SMEM_TOTAL);
    cudaFuncSetAttribute(mlp_kernel<1>, cudaFuncAttributeMaxDynamicSharedMemorySize, SMEM_TOTAL);

    cudaMemcpyAsync(out_mol, mol, (size_t)n_mol * sizeof(float), cudaMemcpyDeviceToDevice);

    prep_split<<<64, 256>>>(w_b1, 0, 256);
    prep_split<<<64, 256>>>(w_s1, 1, 256);
    prep_split<<<64, 256>>>(w_s2, 2, 105);

    int nbB = (2 * n_bonds) / 128;
    int nsB = n_stems / 128;
    mlp_kernel<0><<<nbB + nsB, TPB, SMEM_TOTAL>>>(
        atom, b_b1, w_b2, b_b2, b_s1, b_s2, slices, bd_b, bonds, st_b, st_a,
        out_bond, out_stem, nbB);
    mlp_kernel<1><<<nsB, TPB, SMEM_TOTAL>>>(
        atom, b_b1, w_b2, b_b2, b_s1, b_s2, slices, bd_b, bonds, st_b, st_a,
        out_bond, out_stem, 0);
}

// round 12
// speedup vs baseline: 2.1412x; 1.2337x over previous
#include <cuda_runtime.h>
#include <cuda_fp16.h>
#include <cstdint>
#include <cstddef>

#define TPB 256
#define NEG_SLOPE 0.01f
#define XSTRB 528                     /* X row stride bytes (256 fp16 + pad) */

/* smem byte offsets (per CTA: 70144 B -> 2 CTAs/SM, reg-capped) */
#define XHI_OFF 0
#define B1_OFF  67584
#define W2_OFF  68608
#define GR_OFF  69632
#define SMEM_TOTAL 70144

__device__ float g_H[(size_t)131072 * 256];
/* B-fragment layout: [widx][kc(16)][nt_g(32)][term(2)][lane(32)] x 8B = 256KB per widx */
__device__ __align__(16) uint8_t g_Wfrag[3 * 262144];

__device__ __forceinline__ uint32_t smem_u32(const void* p) {
    uint32_t a;
    asm("{ .reg .u64 t; cvta.to.shared.u64 t, %1; cvt.u32.u64 %0, t; }" : "=r"(a) : "l"(p));
    return a;
}
__device__ __forceinline__ float lrelu(float x) {
    return fmaxf(x, 0.f) + NEG_SLOPE * fminf(x, 0.f);
}
__device__ __forceinline__ uint32_t pack_h2(float v0, float v1) {
    __half2 h = __floats2half2_rn(v0, v1);
    return *(uint32_t*)&h;
}
__device__ __forceinline__ void mma16816(float* c, const uint32_t* a, uint32_t b0, uint32_t b1) {
    asm("mma.sync.aligned.m16n8k16.row.col.f32.f16.f16.f32 "
        "{%0,%1,%2,%3},{%4,%5,%6,%7},{%8,%9},{%0,%1,%2,%3};"
        : "+f"(c[0]), "+f"(c[1]), "+f"(c[2]), "+f"(c[3])
        : "r"(a[0]), "r"(a[1]), "r"(a[2]), "r"(a[3]), "r"(b0), "r"(b1));
}
#define LDM_X4(r, a) \
    asm volatile("ldmatrix.sync.aligned.m8n8.x4.shared.b16 {%0,%1,%2,%3}, [%4];" \
        : "=r"((r)[0]), "=r"((r)[1]), "=r"((r)[2]), "=r"((r)[3]) : "r"(a))

/* ---- prep: W[rows<=256][256] fp32 -> fp16 hi/lo B-register fragments ----
   PTX m16n8k16 B layout: lane l holds n = nt*8 + (l>>2);
   b0 = {W[n][k0], W[n][k0+1]}, b1 = {W[n][k0+8], W[n][k0+9]}, k0 = kc*16 + 2*(l&3). */
__global__ void prep_frag(const float* __restrict__ W, int which, int wrows) {
    int e = blockIdx.x * blockDim.x + threadIdx.x;    /* 0..32767 */
    int lane = e & 31, term = (e >> 5) & 1, nt = (e >> 6) & 31, kc = e >> 11;
    int n = nt * 8 + (lane >> 2);
    int k0 = kc * 16 + 2 * (lane & 3);
    float v0 = 0.f, v1 = 0.f, v8 = 0.f, v9 = 0.f;
    if (n < wrows) {
        const float* src = W + (size_t)n * 256 + k0;
        v0 = src[0]; v1 = src[1]; v8 = src[8]; v9 = src[9];
    }
    uint32_t b0, b1;
    if (term == 0) {
        b0 = pack_h2(v0, v1);
        b1 = pack_h2(v8, v9);
    } else {
        __half2 h0 = __floats2half2_rn(v0, v1); float2 f0 = __half22float2(h0);
        __half2 h1 = __floats2half2_rn(v8, v9); float2 f1 = __half22float2(h1);
        b0 = pack_h2(v0 - f0.x, v1 - f0.y);
        b1 = pack_h2(v8 - f1.x, v9 - f1.y);
    }
    size_t off = ((size_t)which << 18) + (size_t)(((kc * 32 + nt) * 2 + term) << 8) + (lane << 3);
    *(uint2*)(g_Wfrag + off) = make_uint2(b0, b1);
}

/* PASS 0: blocks [0,nbB) bond head, [nbB,..) stems L1 -> g_H | PASS 1: stems L2 */
template<int PASS>
__global__ void __launch_bounds__(TPB, 2)
mlp_kernel(const float* __restrict__ atom,
           const float* __restrict__ b_b1, const float* __restrict__ w_b2,
           const float* __restrict__ b_b2, const float* __restrict__ b_s1,
           const float* __restrict__ b_s2, const int* __restrict__ slices,
           const int* __restrict__ bd_b, const int* __restrict__ bonds,
           const int* __restrict__ st_b, const int* __restrict__ st_a,
           float* __restrict__ out_bond, float* __restrict__ out_stem, int nbB) {
    constexpr int NH = (PASS == 1) ? 1 : 2;
    constexpr int NITER = NH * 16;
    extern __shared__ char sm[];
    uint32_t sb = smem_u32(sm);
    int tid = threadIdx.x, lid = tid & 31, wid = tid >> 5;
    int wm = wid & 1, wn = wid >> 1;
    int mode = (PASS == 1) ? 2 : ((int)blockIdx.x < nbB ? 1 : 0);
    int row_base = (PASS == 1) ? blockIdx.x * 128
                 : (mode == 1 ? blockIdx.x * 128 : (blockIdx.x - nbB) * 128);
    int widx = (PASS == 1) ? 2 : (mode == 1 ? 0 : 1);
    /* warp-constant fragment base: + wn slice + lane */
    const uint8_t* wbase = g_Wfrag + ((size_t)widx << 18) + (wn << 11) + (lid << 3);

    int*   grow = (int*)(sm + GR_OFF);
    float* b1s  = (float*)(sm + B1_OFF);
    float* w2s  = (float*)(sm + W2_OFF);

    if (tid < 128) {
        int r = row_base + tid, g;
        if (PASS == 1)       g = r;
        else if (mode == 1)  { int bd = r >> 1; g = slices[bd_b[bd]] + bonds[2 * bd + (r & 1)]; }
        else                 g = slices[st_b[r]] + st_a[r];
        grow[tid] = g;
    }
    if (PASS == 1) b1s[tid] = (tid < 105) ? b_s2[tid] : 0.f;
    else           b1s[tid] = (mode == 1) ? b_b1[tid] : b_s1[tid];
    if (PASS == 0 && mode == 1) w2s[tid] = w_b2[tid];
    __syncthreads();

    /* ---- X gather + fp16-hi store: thread = (row, half = 128 floats) ---- */
    {
        const float* Asrc = (PASS == 1) ? (const float*)g_H : atom;
        int row = tid >> 1, h = tid & 1;
        const float4* src = (const float4*)(Asrc + (size_t)grow[row] * 256 + h * 128);
        char* xh = sm + XHI_OFF + row * XSTRB + h * 256;
#pragma unroll
        for (int q = 0; q < 32; q++) {
            float4 v = src[q];
            *(uint2*)(xh + q * 8) = make_uint2(pack_h2(v.x, v.y), pack_h2(v.z, v.w));
        }
    }
    __syncthreads();    /* X visible; NO further mainloop barriers */

    float acc[4][4][4];
#pragma unroll
    for (int mt = 0; mt < 4; mt++)
#pragma unroll
        for (int nt = 0; nt < 4; nt++)
#pragma unroll
            for (int j = 0; j < 4; j++) acc[mt][nt][j] = 0.f;
    float ybond[8];
#pragma unroll
    for (int i = 0; i < 8; i++) ybond[i] = 0.f;

    int qr = lid >> 2, qc = lid & 3;
    uint32_t xab = sb + XHI_OFF + (uint32_t)(wm * 64 + (lid & 15)) * XSTRB + ((lid >> 4) << 4);

    /* B fragment regs: [nt] hi, [4+nt] lo */
    uint2 Bc[8];
#pragma unroll
    for (int nt = 0; nt < 4; nt++) {
        const uint8_t* p = wbase;                      /* it = 0 */
        Bc[nt]     = *(const uint2*)(p + nt * 512);
        Bc[4 + nt] = *(const uint2*)(p + nt * 512 + 256);
    }

#pragma unroll 1
    for (int nh = 0; nh < NH; nh++) {
#pragma unroll 4
        for (int kc = 0; kc < 16; kc++) {
            int it = nh * 16 + kc;
            uint2 Bn[8];
            /* first m-tile's MMAs, then prefetch next-iter B, then rest */
            uint32_t ah[4];
            LDM_X4(ah, xab + kc * 32);
#pragma unroll
            for (int nt = 0; nt < 4; nt++) {
                mma16816(acc[0][nt], ah, Bc[nt].x, Bc[nt].y);
                mma16816(acc[0][nt], ah, Bc[4 + nt].x, Bc[4 + nt].y);
            }
            if (it + 1 < NITER) {
                int it2 = it + 1;
                const uint8_t* p = wbase + (size_t)((it2 & 15) << 14) + (size_t)((it2 >> 4) << 13);
#pragma unroll
                for (int nt = 0; nt < 4; nt++) {
                    Bn[nt]     = *(const uint2*)(p + nt * 512);
                    Bn[4 + nt] = *(const uint2*)(p + nt * 512 + 256);
                }
            }
#pragma unroll
            for (int mt = 1; mt < 4; mt++) {
                LDM_X4(ah, xab + mt * (16 * XSTRB) + kc * 32);
#pragma unroll
                for (int nt = 0; nt < 4; nt++) {
                    mma16816(acc[mt][nt], ah, Bc[nt].x, Bc[nt].y);
                    mma16816(acc[mt][nt], ah, Bc[4 + nt].x, Bc[4 + nt].y);
                }
            }
            if (it + 1 < NITER) {
#pragma unroll
                for (int i = 0; i < 8; i++) Bc[i] = Bn[i];
            }
        }
        /* ---- half-epilogue on N-half nh ---- */
        if (PASS == 0 && mode == 1) {
#pragma unroll
            for (int mt = 0; mt < 4; mt++)
#pragma unroll
                for (int jr = 0; jr < 2; jr++) {
                    float s = 0.f;
#pragma unroll
                    for (int nt = 0; nt < 4; nt++) {
                        int c = nh * 128 + wn * 32 + nt * 8 + 2 * qc;
                        s += lrelu(acc[mt][nt][2 * jr]     + b1s[c])     * w2s[c];
                        s += lrelu(acc[mt][nt][2 * jr + 1] + b1s[c + 1]) * w2s[c + 1];
                    }
                    ybond[mt * 2 + jr] += s;
                }
        } else if (PASS == 0) { /* stems L1 */
#pragma unroll
            for (int mt = 0; mt < 4; mt++)
#pragma unroll
                for (int jr = 0; jr < 2; jr++) {
                    size_t row = (size_t)row_base + wm * 64 + mt * 16 + qr + 8 * jr;
#pragma unroll
                    for (int nt = 0; nt < 4; nt++) {
                        int c = nh * 128 + wn * 32 + nt * 8 + 2 * qc;
                        float v0 = lrelu(acc[mt][nt][2 * jr]     + b1s[c]);
                        float v1 = lrelu(acc[mt][nt][2 * jr + 1] + b1s[c + 1]);
                        *(float2*)(g_H + row * 256 + c) = make_float2(v0, v1);
                    }
                }
        } else { /* PASS 1 */
#pragma unroll
            for (int mt = 0; mt < 4; mt++)
#pragma unroll
                for (int jr = 0; jr < 2; jr++) {
                    size_t row = (size_t)row_base + wm * 64 + mt * 16 + qr + 8 * jr;
#pragma unroll
                    for (int nt = 0; nt < 4; nt++) {
                        int c = wn * 32 + nt * 8 + 2 * qc;
                        if (c < 105)
                            out_stem[row * 105 + c] = acc[mt][nt][2 * jr] + b1s[c];
                        if (c + 1 < 105)
                            out_stem[row * 105 + c + 1] = acc[mt][nt][2 * jr + 1] + b1s[c + 1];
                    }
                }
        }
        if (nh == 0 && NH == 2) {
#pragma unroll
            for (int mt = 0; mt < 4; mt++)
#pragma unroll
                for (int nt = 0; nt < 4; nt++)
#pragma unroll
                    for (int j = 0; j < 4; j++) acc[mt][nt][j] = 0.f;
        }
    }

    /* ---- bond final reduce across warps ---- */
    if (PASS == 0 && mode == 1) {
        __syncthreads();                       /* X reads done everywhere */
        float* ysm = (float*)(sm + XHI_OFF);   /* reuse X area: [4 wn][128 rows] */
#pragma unroll
        for (int mt = 0; mt < 4; mt++)
#pragma unroll
            for (int jr = 0; jr < 2; jr++) {
                float s = ybond[mt * 2 + jr];
                s += __shfl_xor_sync(0xffffffffu, s, 1);
                s += __shfl_xor_sync(0xffffffffu, s, 2);
                if (qc == 0)
                    ysm[wn * 128 + wm * 64 + mt * 16 + qr + 8 * jr] = s;
            }
        __syncthreads();
        if (tid < 128) {
            float y = ysm[tid] + ysm[128 + tid] + ysm[256 + tid] + ysm[384 + tid];
            float y2 = __shfl_down_sync(0xffffffffu, y, 1);
            if (!(tid & 1))
                out_bond[(row_base + tid) >> 1] = 0.5f * (y + y2) + b_b2[0];
        }
    }
}

extern "C" void kernel_launch(void* const* d_in, const int* in_sizes, int n_in,
                              void* d_out, int out_size) {
    const float* atom = (const float*)d_in[0];
    const float* mol  = (const float*)d_in[1];
    const float* w_s1 = (const float*)d_in[2];
    const float* b_s1 = (const float*)d_in[3];
    const float* w_s2 = (const float*)d_in[4];
    const float* b_s2 = (const float*)d_in[5];
    const float* w_b1 = (const float*)d_in[6];
    const float* b_b1 = (const float*)d_in[7];
    const float* w_b2 = (const float*)d_in[8];
    const float* b_b2 = (const float*)d_in[9];
    const int* slices = (const int*)d_in[10];
    const int* st_b   = (const int*)d_in[11];
    const int* st_a   = (const int*)d_in[12];
    const int* bonds  = (const int*)d_in[13];
    const int* bd_b   = (const int*)d_in[14];

    int n_stems = in_sizes[11];
    int n_mol   = in_sizes[1];
    int n_bonds = in_sizes[14];

    float* out      = (float*)d_out;
    float* out_stem = out;
    float* out_mol  = out + (size_t)n_stems * 105;
    float* out_bond = out_mol + n_mol;

    cudaFuncSetAttribute(mlp_kernel<0>, cudaFuncAttributeMaxDynamicSharedMemorySize, SMEM_TOTAL);
    cudaFuncSetAttribute(mlp_kernel<1>, cudaFuncAttributeMaxDynamicSharedMemorySize, SMEM_TOTAL);

    cudaMemcpyAsync(out_mol, mol, (size_t)n_mol * sizeof(float), cudaMemcpyDeviceToDevice);

    prep_frag<<<128, 256>>>(w_b1, 0, 256);
    prep_frag<<<128, 256>>>(w_s1, 1, 256);
    prep_frag<<<128, 256>>>(w_s2, 2, 105);

    int nbB = (2 * n_bonds) / 128;
    int nsB = n_stems / 128;
    mlp_kernel<0><<<nbB + nsB, TPB, SMEM_TOTAL>>>(
        atom, b_b1, w_b2, b_b2, b_s1, b_s2, slices, bd_b, bonds, st_b, st_a,
        out_bond, out_stem, nbB);
    mlp_kernel<1><<<nsB, TPB, SMEM_TOTAL>>>(
        atom, b_b1, w_b2, b_b2, b_s1, b_s2, slices, bd_b, bonds, st_b, st_a,
        out_bond, out_stem, 0);
}

// round 13
// speedup vs baseline: 3.0587x; 1.4285x over previous
#include <cuda_runtime.h>
#include <cuda_fp16.h>
#include <cstdint>
#include <cstddef>

#define TPB 256
#define NEG_SLOPE 0.01f
#define XSTRB 528                     /* X row stride bytes (256 fp16 + pad) */

/* smem byte offsets (per CTA: 70144 B -> 2 CTAs/SM) */
#define XHI_OFF 0
#define B1_OFF  67584
#define W2_OFF  68608
#define GR_OFF  69632
#define SMEM_TOTAL 70144

__device__ float g_H[(size_t)131072 * 256];
/* B-fragment layout: [widx][kc(16)][nt_g(32)][term(2)][lane(32)] x 8B = 256KB per widx */
__device__ __align__(16) uint8_t g_Wfrag[3 * 262144];

__device__ __forceinline__ uint32_t smem_u32(const void* p) {
    uint32_t a;
    asm("{ .reg .u64 t; cvta.to.shared.u64 t, %1; cvt.u32.u64 %0, t; }" : "=r"(a) : "l"(p));
    return a;
}
__device__ __forceinline__ float lrelu(float x) {
    return fmaxf(x, 0.f) + NEG_SLOPE * fminf(x, 0.f);
}
__device__ __forceinline__ uint32_t pack_h2(float v0, float v1) {
    __half2 h = __floats2half2_rn(v0, v1);
    return *(uint32_t*)&h;
}
__device__ __forceinline__ void mma16816(float* c, const uint32_t* a, uint32_t b0, uint32_t b1) {
    asm("mma.sync.aligned.m16n8k16.row.col.f32.f16.f16.f32 "
        "{%0,%1,%2,%3},{%4,%5,%6,%7},{%8,%9},{%0,%1,%2,%3};"
        : "+f"(c[0]), "+f"(c[1]), "+f"(c[2]), "+f"(c[3])
        : "r"(a[0]), "r"(a[1]), "r"(a[2]), "r"(a[3]), "r"(b0), "r"(b1));
}
#define LDM_X4(r, a) \
    asm volatile("ldmatrix.sync.aligned.m8n8.x4.shared.b16 {%0,%1,%2,%3}, [%4];" \
        : "=r"((r)[0]), "=r"((r)[1]), "=r"((r)[2]), "=r"((r)[3]) : "r"(a))

/* ---- prep: W[rows<=256][256] fp32 -> fp16 hi/lo B-register fragments ----
   (lo entries still emitted; mainloop reads hi only) */
__global__ void prep_frag(const float* __restrict__ W, int which, int wrows) {
    int e = blockIdx.x * blockDim.x + threadIdx.x;    /* 0..32767 */
    int lane = e & 31, term = (e >> 5) & 1, nt = (e >> 6) & 31, kc = e >> 11;
    int n = nt * 8 + (lane >> 2);
    int k0 = kc * 16 + 2 * (lane & 3);
    float v0 = 0.f, v1 = 0.f, v8 = 0.f, v9 = 0.f;
    if (n < wrows) {
        const float* src = W + (size_t)n * 256 + k0;
        v0 = src[0]; v1 = src[1]; v8 = src[8]; v9 = src[9];
    }
    uint32_t b0, b1;
    if (term == 0) {
        b0 = pack_h2(v0, v1);
        b1 = pack_h2(v8, v9);
    } else {
        __half2 h0 = __floats2half2_rn(v0, v1); float2 f0 = __half22float2(h0);
        __half2 h1 = __floats2half2_rn(v8, v9); float2 f1 = __half22float2(h1);
        b0 = pack_h2(v0 - f0.x, v1 - f0.y);
        b1 = pack_h2(v8 - f1.x, v9 - f1.y);
    }
    size_t off = ((size_t)which << 18) + (size_t)(((kc * 32 + nt) * 2 + term) << 8) + (lane << 3);
    *(uint2*)(g_Wfrag + off) = make_uint2(b0, b1);
}

/* PASS 0: blocks [0,nbB) bond head, [nbB,..) stems L1 -> g_H | PASS 1: stems L2 */
template<int PASS>
__global__ void __launch_bounds__(TPB, 2)
mlp_kernel(const float* __restrict__ atom,
           const float* __restrict__ b_b1, const float* __restrict__ w_b2,
           const float* __restrict__ b_b2, const float* __restrict__ b_s1,
           const float* __restrict__ b_s2, const int* __restrict__ slices,
           const int* __restrict__ bd_b, const int* __restrict__ bonds,
           const int* __restrict__ st_b, const int* __restrict__ st_a,
           float* __restrict__ out_bond, float* __restrict__ out_stem, int nbB) {
    constexpr int NH = (PASS == 1) ? 1 : 2;
    constexpr int NITER = NH * 16;
    extern __shared__ char sm[];
    uint32_t sb = smem_u32(sm);
    int tid = threadIdx.x, lid = tid & 31, wid = tid >> 5;
    int wm = wid & 1, wn = wid >> 1;
    int mode = (PASS == 1) ? 2 : ((int)blockIdx.x < nbB ? 1 : 0);
    int row_base = (PASS == 1) ? blockIdx.x * 128
                 : (mode == 1 ? blockIdx.x * 128 : (blockIdx.x - nbB) * 128);
    int widx = (PASS == 1) ? 2 : (mode == 1 ? 0 : 1);
    const uint8_t* wbase = g_Wfrag + ((size_t)widx << 18) + (wn << 11) + (lid << 3);

    int*   grow = (int*)(sm + GR_OFF);
    float* b1s  = (float*)(sm + B1_OFF);
    float* w2s  = (float*)(sm + W2_OFF);

    if (tid < 128) {
        int r = row_base + tid, g;
        if (PASS == 1)       g = r;
        else if (mode == 1)  { int bd = r >> 1; g = slices[bd_b[bd]] + bonds[2 * bd + (r & 1)]; }
        else                 g = slices[st_b[r]] + st_a[r];
        grow[tid] = g;
    }
    if (PASS == 1) b1s[tid] = (tid < 105) ? b_s2[tid] : 0.f;
    else           b1s[tid] = (mode == 1) ? b_b1[tid] : b_s1[tid];
    if (PASS == 0 && mode == 1) w2s[tid] = w_b2[tid];
    __syncthreads();

    /* ---- X gather + fp16-hi store: thread = (row, half = 128 floats) ---- */
    {
        const float* Asrc = (PASS == 1) ? (const float*)g_H : atom;
        int row = tid >> 1, h = tid & 1;
        const float4* src = (const float4*)(Asrc + (size_t)grow[row] * 256 + h * 128);
        char* xh = sm + XHI_OFF + row * XSTRB + h * 256;
#pragma unroll
        for (int q = 0; q < 32; q++) {
            float4 v = src[q];
            *(uint2*)(xh + q * 8) = make_uint2(pack_h2(v.x, v.y), pack_h2(v.z, v.w));
        }
    }
    __syncthreads();    /* X visible; NO further mainloop barriers */

    float acc[4][4][4];
#pragma unroll
    for (int mt = 0; mt < 4; mt++)
#pragma unroll
        for (int nt = 0; nt < 4; nt++)
#pragma unroll
            for (int j = 0; j < 4; j++) acc[mt][nt][j] = 0.f;
    float ybond[8];
#pragma unroll
    for (int i = 0; i < 8; i++) ybond[i] = 0.f;

    int qr = lid >> 2, qc = lid & 3;
    uint32_t xab = sb + XHI_OFF + (uint32_t)(wm * 64 + (lid & 15)) * XSTRB + ((lid >> 4) << 4);

    /* B hi-fragment regs only (1-term) */
    uint2 Bc[4];
#pragma unroll
    for (int nt = 0; nt < 4; nt++)
        Bc[nt] = *(const uint2*)(wbase + nt * 512);

#pragma unroll 1
    for (int nh = 0; nh < NH; nh++) {
#pragma unroll 4
        for (int kc = 0; kc < 16; kc++) {
            int it = nh * 16 + kc;
            uint2 Bn[4];
            uint32_t ah[4];
            LDM_X4(ah, xab + kc * 32);
#pragma unroll
            for (int nt = 0; nt < 4; nt++)
                mma16816(acc[0][nt], ah, Bc[nt].x, Bc[nt].y);
            if (it + 1 < NITER) {
                int it2 = it + 1;
                const uint8_t* p = wbase + (size_t)((it2 & 15) << 14) + (size_t)((it2 >> 4) << 13);
#pragma unroll
                for (int nt = 0; nt < 4; nt++)
                    Bn[nt] = *(const uint2*)(p + nt * 512);
            }
#pragma unroll
            for (int mt = 1; mt < 4; mt++) {
                LDM_X4(ah, xab + mt * (16 * XSTRB) + kc * 32);
#pragma unroll
                for (int nt = 0; nt < 4; nt++)
                    mma16816(acc[mt][nt], ah, Bc[nt].x, Bc[nt].y);
            }
            if (it + 1 < NITER) {
#pragma unroll
                for (int i = 0; i < 4; i++) Bc[i] = Bn[i];
            }
        }
        /* ---- half-epilogue on N-half nh ---- */
        if (PASS == 0 && mode == 1) {
#pragma unroll
            for (int mt = 0; mt < 4; mt++)
#pragma unroll
                for (int jr = 0; jr < 2; jr++) {
                    float s = 0.f;
#pragma unroll
                    for (int nt = 0; nt < 4; nt++) {
                        int c = nh * 128 + wn * 32 + nt * 8 + 2 * qc;
                        s += lrelu(acc[mt][nt][2 * jr]     + b1s[c])     * w2s[c];
                        s += lrelu(acc[mt][nt][2 * jr + 1] + b1s[c + 1]) * w2s[c + 1];
                    }
                    ybond[mt * 2 + jr] += s;
                }
        } else if (PASS == 0) { /* stems L1 */
#pragma unroll
            for (int mt = 0; mt < 4; mt++)
#pragma unroll
                for (int jr = 0; jr < 2; jr++) {
                    size_t row = (size_t)row_base + wm * 64 + mt * 16 + qr + 8 * jr;
#pragma unroll
                    for (int nt = 0; nt < 4; nt++) {
                        int c = nh * 128 + wn * 32 + nt * 8 + 2 * qc;
                        float v0 = lrelu(acc[mt][nt][2 * jr]     + b1s[c]);
                        float v1 = lrelu(acc[mt][nt][2 * jr + 1] + b1s[c + 1]);
                        *(float2*)(g_H + row * 256 + c) = make_float2(v0, v1);
                    }
                }
        } else { /* PASS 1 */
#pragma unroll
            for (int mt = 0; mt < 4; mt++)
#pragma unroll
                for (int jr = 0; jr < 2; jr++) {
                    size_t row = (size_t)row_base + wm * 64 + mt * 16 + qr + 8 * jr;
#pragma unroll
                    for (int nt = 0; nt < 4; nt++) {
                        int c = wn * 32 + nt * 8 + 2 * qc;
                        if (c < 105)
                            out_stem[row * 105 + c] = acc[mt][nt][2 * jr] + b1s[c];
                        if (c + 1 < 105)
                            out_stem[row * 105 + c + 1] = acc[mt][nt][2 * jr + 1] + b1s[c + 1];
                    }
                }
        }
        if (nh == 0 && NH == 2) {
#pragma unroll
            for (int mt = 0; mt < 4; mt++)
#pragma unroll
                for (int nt = 0; nt < 4; nt++)
#pragma unroll
                    for (int j = 0; j < 4; j++) acc[mt][nt][j] = 0.f;
        }
    }

    /* ---- bond final reduce across warps ---- */
    if (PASS == 0 && mode == 1) {
        __syncthreads();
        float* ysm = (float*)(sm + XHI_OFF);   /* reuse X area: [4 wn][128 rows] */
#pragma unroll
        for (int mt = 0; mt < 4; mt++)
#pragma unroll
            for (int jr = 0; jr < 2; jr++) {
                float s = ybond[mt * 2 + jr];
                s += __shfl_xor_sync(0xffffffffu, s, 1);
                s += __shfl_xor_sync(0xffffffffu, s, 2);
                if (qc == 0)
                    ysm[wn * 128 + wm * 64 + mt * 16 + qr + 8 * jr] = s;
            }
        __syncthreads();
        if (tid < 128) {
            float y = ysm[tid] + ysm[128 + tid] + ysm[256 + tid] + ysm[384 + tid];
            float y2 = __shfl_down_sync(0xffffffffu, y, 1);
            if (!(tid & 1))
                out_bond[(row_base + tid) >> 1] = 0.5f * (y + y2) + b_b2[0];
        }
    }
}

extern "C" void kernel_launch(void* const* d_in, const int* in_sizes, int n_in,
                              void* d_out, int out_size) {
    const float* atom = (const float*)d_in[0];
    const float* mol  = (const float*)d_in[1];
    const float* w_s1 = (const float*)d_in[2];
    const float* b_s1 = (const float*)d_in[3];
    const float* w_s2 = (const float*)d_in[4];
    const float* b_s2 = (const float*)d_in[5];
    const float* w_b1 = (const float*)d_in[6];
    const float* b_b1 = (const float*)d_in[7];
    const float* w_b2 = (const float*)d_in[8];
    const float* b_b2 = (const float*)d_in[9];
    const int* slices = (const int*)d_in[10];
    const int* st_b   = (const int*)d_in[11];
    const int* st_a   = (const int*)d_in[12];
    const int* bonds  = (const int*)d_in[13];
    const int* bd_b   = (const int*)d_in[14];

    int n_stems = in_sizes[11];
    int n_mol   = in_sizes[1];
    int n_bonds = in_sizes[14];

    float* out      = (float*)d_out;
    float* out_stem = out;
    float* out_mol  = out + (size_t)n_stems * 105;
    float* out_bond = out_mol + n_mol;

    cudaFuncSetAttribute(mlp_kernel<0>, cudaFuncAttributeMaxDynamicSharedMemorySize, SMEM_TOTAL);
    cudaFuncSetAttribute(mlp_kernel<1>, cudaFuncAttributeMaxDynamicSharedMemorySize, SMEM_TOTAL);

    cudaMemcpyAsync(out_mol, mol, (size_t)n_mol * sizeof(float), cudaMemcpyDeviceToDevice);

    prep_frag<<<128, 256>>>(w_b1, 0, 256);
    prep_frag<<<128, 256>>>(w_s1, 1, 256);
    prep_frag<<<128, 256>>>(w_s2, 2, 105);

    int nbB = (2 * n_bonds) / 128;
    int nsB = n_stems / 128;
    mlp_kernel<0><<<nbB + nsB, TPB, SMEM_TOTAL>>>(
        atom, b_b1, w_b2, b_b2, b_s1, b_s2, slices, bd_b, bonds, st_b, st_a,
        out_bond, out_stem, nbB);
    mlp_kernel<1><<<nsB, TPB, SMEM_TOTAL>>>(
        atom, b_b1, w_b2, b_b2, b_s1, b_s2, slices, bd_b, bonds, st_b, st_a,
        out_bond, out_stem, 0);
}